// round 8
// baseline (speedup 1.0000x reference)
#include <cuda_runtime.h>
#include <cuda_bf16.h>
#include <cstdint>

#define N_USER 100000
#define N_ITEM 50000
#define N_NODES 150000
#define N_EDGES 1200000
#define D 64
#define OUTD 256
#define NEG_SLOPE 0.01f
#define EPS_NORM 1e-12f

#define SCAN_BLK 1024
#define SCAN_NBLK ((N_NODES + SCAN_BLK - 1) / SCAN_BLK)   // 147

// Scratch (device globals; no dynamic allocation)
__device__ float g_EA[N_NODES * D];       // E ping
__device__ float g_EB[N_NODES * D];       // E pong
__device__ float4 g_Wpack[3 * 2048];      // packed W quads per layer
__device__ int g_cnt[N_NODES];
__device__ int g_off[N_NODES + 1];
__device__ int g_cur[N_NODES];
__device__ float2 g_edge[N_EDGES];        // {bitcast(col), val}
__device__ int g_blksum[SCAN_NBLK];

// ---------------------------------------------------------------------------
// helpers
// ---------------------------------------------------------------------------
__device__ __forceinline__ float lrelu(float v) {
    return v >= 0.f ? v : NEG_SLOPE * v;
}
__device__ __forceinline__ unsigned long long pk2(float lo, float hi) {
    unsigned long long r;
    asm("mov.b64 %0, {%1, %2};" : "=l"(r) : "f"(lo), "f"(hi));
    return r;
}
__device__ __forceinline__ void unpk2(float& lo, float& hi, unsigned long long v) {
    asm("mov.b64 {%0, %1}, %2;" : "=f"(lo), "=f"(hi) : "l"(v));
}
__device__ __forceinline__ void fma2(unsigned long long& d, unsigned long long a,
                                     unsigned long long b) {
    asm("fma.rn.f32x2 %0, %1, %2, %0;" : "+l"(d) : "l"(a), "l"(b));
}

// ---------------------------------------------------------------------------
// CSR build: zero -> hist -> scan(3) -> scatter
// ---------------------------------------------------------------------------
__global__ void k_zero() {
    int i = blockIdx.x * blockDim.x + threadIdx.x;
    if (i < N_NODES) g_cnt[i] = 0;
}
__global__ void k_hist(const int* __restrict__ erow) {
    int e = blockIdx.x * blockDim.x + threadIdx.x;
    if (e >= N_EDGES) return;
    atomicAdd(&g_cnt[__ldg(&erow[e])], 1);
}
__global__ void k_scan1() {   // warp-scan based block scan
    __shared__ int wsum[32];
    int i = blockIdx.x * SCAN_BLK + threadIdx.x;
    int lane = threadIdx.x & 31;
    int wid = threadIdx.x >> 5;
    int v = (i < N_NODES) ? g_cnt[i] : 0;
    int s = v;
    #pragma unroll
    for (int d = 1; d < 32; d <<= 1) {
        int t = __shfl_up_sync(0xffffffffu, s, d);
        if (lane >= d) s += t;
    }
    if (lane == 31) wsum[wid] = s;
    __syncthreads();
    if (wid == 0) {
        int w = wsum[lane];
        #pragma unroll
        for (int d = 1; d < 32; d <<= 1) {
            int t = __shfl_up_sync(0xffffffffu, w, d);
            if (lane >= d) w += t;
        }
        wsum[lane] = w;
    }
    __syncthreads();
    int incl = s + (wid ? wsum[wid - 1] : 0);
    if (i < N_NODES) g_off[i] = incl - v;              // exclusive within block
    if (threadIdx.x == SCAN_BLK - 1) g_blksum[blockIdx.x] = incl;
}
__global__ void k_scan2() {   // one block of 256; shfl 2-level scan
    __shared__ int wsum[8];
    int lane = threadIdx.x & 31;
    int wid = threadIdx.x >> 5;
    int v = (threadIdx.x < SCAN_NBLK) ? g_blksum[threadIdx.x] : 0;
    int s = v;
    #pragma unroll
    for (int d = 1; d < 32; d <<= 1) {
        int t = __shfl_up_sync(0xffffffffu, s, d);
        if (lane >= d) s += t;
    }
    if (lane == 31) wsum[wid] = s;
    __syncthreads();
    int add = 0;
    #pragma unroll
    for (int w = 0; w < 8; w++)
        if (w < wid) add += wsum[w];
    if (threadIdx.x < SCAN_NBLK) g_blksum[threadIdx.x] = s + add - v;
}
__global__ void k_scan3() {
    int i = blockIdx.x * SCAN_BLK + threadIdx.x;
    if (i >= N_NODES) return;
    int o = g_off[i] + g_blksum[i >> 10];
    g_off[i] = o;
    g_cur[i] = o;
    if (i == 0) g_off[N_NODES] = N_EDGES;
}
__global__ void k_scatter(const int* __restrict__ erow, const int* __restrict__ ecol,
                          const float* __restrict__ eval_) {
    int e = blockIdx.x * blockDim.x + threadIdx.x;
    if (e >= N_EDGES) return;
    int r = __ldg(&erow[e]);
    int pos = atomicAdd(&g_cur[r], 1);
    g_edge[pos] = make_float2(__int_as_float(__ldg(&ecol[e])), __ldg(&eval_[e]));
}

// ---------------------------------------------------------------------------
// kernel P: pack W for all 3 layers
// g_Wpack[l*2048 + k*32 + j] = { Wf[j][k], Wf[j+32][k], Wb[j][k], Wb[j+32][k] }
// ---------------------------------------------------------------------------
__global__ void k_prep(const float* __restrict__ Wf, const float* __restrict__ Wb) {
    int u = blockIdx.x * blockDim.x + threadIdx.x;
    if (u >= 3 * 2048) return;
    int l = u >> 11;
    int t = u & 2047;
    int k = t >> 5;
    int j = t & 31;
    const float* wf = Wf + l * D * D;
    const float* wb = Wb + l * D * D;
    g_Wpack[u] = make_float4(wf[j * D + k], wf[(j + 32) * D + k],
                             wb[j * D + k], wb[(j + 32) * D + k]);
}

// ---------------------------------------------------------------------------
// kernel 0: build E0 = concat(user, item) into g_EA; write out[:, 0:64]
// ---------------------------------------------------------------------------
__global__ void k_init(const float* __restrict__ user, const float* __restrict__ item,
                       float* __restrict__ out) {
    int idx = blockIdx.x * blockDim.x + threadIdx.x;
    if (idx >= N_NODES * (D / 4)) return;
    int row = idx >> 4;
    int c4 = (idx & 15) << 2;
    float4 v;
    if (row < N_USER)
        v = *reinterpret_cast<const float4*>(&user[row * D + c4]);
    else
        v = *reinterpret_cast<const float4*>(&item[(row - N_USER) * D + c4]);
    *reinterpret_cast<float4*>(&g_EA[row * D + c4]) = v;
    *reinterpret_cast<float4*>(&out[row * OUTD + c4]) = v;
}

// ---------------------------------------------------------------------------
// fused layer kernel: spmm (CSR gather, registers) + dense + norm.
// blockDim (32,8); each warp processes 2 groups of 8 rows (pass loop).
// W copied + synced BEFORE gather, so warps flow gather->dense independently
// (phase mixing across warps on the SM).
// ---------------------------------------------------------------------------
#define GROUPS (N_NODES / 8)                  // 18750
#define LAYER_WARPS 8
#define GROUPS_PER_WARP 2
#define GROUPS_PER_BLOCK (LAYER_WARPS * GROUPS_PER_WARP)   // 16
#define LAYER_BLOCKS ((GROUPS + GROUPS_PER_BLOCK - 1) / GROUPS_PER_BLOCK)  // 1172

__global__ __launch_bounds__(32 * LAYER_WARPS) void k_layer(
        const float* __restrict__ bf, const float* __restrict__ bb,
        float* __restrict__ out, int layer, int flip, int keepE) {
    __shared__ float4 Wc[D * 32];                    // 32 KB, packed quads
    __shared__ float4 xy[LAYER_WARPS][4][D];         // 32 KB

    const float* Ein = flip ? g_EB : g_EA;
    float* Eout = flip ? g_EA : g_EB;

    int tid = threadIdx.y * 32 + threadIdx.x;
    int lane = threadIdx.x;
    int ty = threadIdx.y;

    // coalesced copy of pre-packed W, synced BEFORE gather
    const float4* wsrc = g_Wpack + layer * 2048;
    #pragma unroll
    for (int t = tid; t < 2048; t += 32 * LAYER_WARPS) Wc[t] = wsrc[t];
    __syncthreads();

    const float2* E2 = reinterpret_cast<const float2*>(Ein);
    float bfv0 = bf[lane], bfv1 = bf[lane + 32];
    float bbv0 = bb[lane], bbv1 = bb[lane + 32];
    int ocol = (layer + 1) * D;

    int gbase = (blockIdx.x * LAYER_WARPS + ty) * GROUPS_PER_WARP;

    #pragma unroll 1
    for (int pass = 0; pass < GROUPS_PER_WARP; pass++) {
        int group = gbase + pass;
        if (group >= GROUPS) break;
        int rb = group * 8;

        __syncwarp();   // xy reuse guard (prev pass reads done)

        // phase 1: gather front for 4 row pairs, stage xy
        #pragma unroll
        for (int p = 0; p < 4; p++) {
            int r0 = rb + 2 * p;
            int r1 = r0 + 1;
            int i0 = __ldg(&g_off[r0]);
            int n0 = __ldg(&g_off[r0 + 1]);
            int i1 = __ldg(&g_off[r1]);
            int n1 = __ldg(&g_off[r1 + 1]);
            float2 e0v = E2[r0 * 32 + lane];
            float2 e1v = E2[r1 * 32 + lane];
            float2 acc0 = e0v;                        // +I term
            float2 acc1 = e1v;
            int m = min(n0 - i0, n1 - i1);
            #pragma unroll 2
            for (int t = 0; t < m; t++) {
                float2 p0 = g_edge[i0 + t];
                float2 p1 = g_edge[i1 + t];
                int c0 = __float_as_int(p0.x);
                int c1 = __float_as_int(p1.x);
                float2 x0 = E2[c0 * 32 + lane];
                float2 x1 = E2[c1 * 32 + lane];
                acc0.x = fmaf(p0.y, x0.x, acc0.x);
                acc0.y = fmaf(p0.y, x0.y, acc0.y);
                acc1.x = fmaf(p1.y, x1.x, acc1.x);
                acc1.y = fmaf(p1.y, x1.y, acc1.y);
            }
            for (i0 += m; i0 < n0; i0++) {
                float2 p0 = g_edge[i0];
                int c0 = __float_as_int(p0.x);
                float2 x0 = E2[c0 * 32 + lane];
                acc0.x = fmaf(p0.y, x0.x, acc0.x);
                acc0.y = fmaf(p0.y, x0.y, acc0.y);
            }
            for (i1 += m; i1 < n1; i1++) {
                float2 p1 = g_edge[i1];
                int c1 = __float_as_int(p1.x);
                float2 x1 = E2[c1 * 32 + lane];
                acc1.x = fmaf(p1.y, x1.x, acc1.x);
                acc1.y = fmaf(p1.y, x1.y, acc1.y);
            }
            xy[ty][p][2 * lane] =
                make_float4(acc0.x, acc1.x, acc0.x * e0v.x, acc1.x * e1v.x);
            xy[ty][p][2 * lane + 1] =
                make_float4(acc0.y, acc1.y, acc0.y * e0v.y, acc1.y * e1v.y);
        }
        __syncwarp();

        // phase 2: dense
        unsigned long long sf0[4], sf1[4], sb0[4], sb1[4];
        #pragma unroll
        for (int p = 0; p < 4; p++) {
            sf0[p] = pk2(bfv0, bfv0);
            sf1[p] = pk2(bfv1, bfv1);
            sb0[p] = pk2(bbv0, bbv0);
            sb1[p] = pk2(bbv1, bbv1);
        }

        #pragma unroll 4
        for (int k = 0; k < D; k++) {
            float4 w = Wc[k * 32 + lane];
            unsigned long long wf0p = pk2(w.x, w.x);
            unsigned long long wf1p = pk2(w.y, w.y);
            unsigned long long wb0p = pk2(w.z, w.z);
            unsigned long long wb1p = pk2(w.w, w.w);
            #pragma unroll
            for (int p = 0; p < 4; p++) {
                ulonglong2 v = *reinterpret_cast<const ulonglong2*>(&xy[ty][p][k]);
                fma2(sf0[p], v.x, wf0p);
                fma2(sf1[p], v.x, wf1p);
                fma2(sb0[p], v.y, wb0p);
                fma2(sb1[p], v.y, wb1p);
            }
        }

        // phase 3: epilogue
        #pragma unroll
        for (int p = 0; p < 4; p++) {
            float f0lo, f0hi, f1lo, f1hi, b0lo, b0hi, b1lo, b1hi;
            unpk2(f0lo, f0hi, sf0[p]);
            unpk2(f1lo, f1hi, sf1[p]);
            unpk2(b0lo, b0hi, sb0[p]);
            unpk2(b1lo, b1hi, sb1[p]);

            int row0 = rb + 2 * p;
            int row1 = row0 + 1;

            float o00 = lrelu(f0lo) + lrelu(b0lo);
            float o01 = lrelu(f1lo) + lrelu(b1lo);
            float o10 = lrelu(f0hi) + lrelu(b0hi);
            float o11 = lrelu(f1hi) + lrelu(b1hi);

            float ss0 = o00 * o00 + o01 * o01;
            float ss1 = o10 * o10 + o11 * o11;
            #pragma unroll
            for (int d = 16; d > 0; d >>= 1) {
                ss0 += __shfl_xor_sync(0xffffffffu, ss0, d);
                ss1 += __shfl_xor_sync(0xffffffffu, ss1, d);
            }
            float inv0 = 1.f / fmaxf(sqrtf(ss0), EPS_NORM);
            float inv1 = 1.f / fmaxf(sqrtf(ss1), EPS_NORM);

            if (keepE) {
                Eout[row0 * D + lane] = o00;
                Eout[row0 * D + 32 + lane] = o01;
                Eout[row1 * D + lane] = o10;
                Eout[row1 * D + 32 + lane] = o11;
            }

            out[row0 * OUTD + ocol + lane] = o00 * inv0;
            out[row0 * OUTD + ocol + 32 + lane] = o01 * inv0;
            out[row1 * OUTD + ocol + lane] = o10 * inv1;
            out[row1 * OUTD + ocol + 32 + lane] = o11 * inv1;
        }
    }
}

// ---------------------------------------------------------------------------
extern "C" void kernel_launch(void* const* d_in, const int* in_sizes, int n_in,
                              void* d_out, int out_size) {
    const float* user = (const float*)d_in[0];
    const float* item = (const float*)d_in[1];
    const int* erow = (const int*)d_in[2];
    const int* ecol = (const int*)d_in[3];
    const float* eval_ = (const float*)d_in[4];
    const float* Wf = (const float*)d_in[5];
    const float* bf = (const float*)d_in[6];
    const float* Wb = (const float*)d_in[7];
    const float* bb = (const float*)d_in[8];
    float* out = (float*)d_out;

    const int vec_elems = N_NODES * (D / 4);
    const int vec_blocks = (vec_elems + 255) / 256;
    const int edge_blocks = (N_EDGES + 255) / 256;
    const int node_blocks = (N_NODES + 255) / 256;

    // CSR build (per replay; deterministic)
    k_zero<<<node_blocks, 256>>>();
    k_hist<<<edge_blocks, 256>>>(erow);
    k_scan1<<<SCAN_NBLK, SCAN_BLK>>>();
    k_scan2<<<1, 256>>>();
    k_scan3<<<SCAN_NBLK, SCAN_BLK>>>();
    k_scatter<<<edge_blocks, 256>>>(erow, ecol, eval_);

    k_prep<<<24, 256>>>(Wf, Wb);
    k_init<<<vec_blocks, 256>>>(user, item, out);
    for (int l = 0; l < 3; l++) {
        k_layer<<<LAYER_BLOCKS, dim3(32, LAYER_WARPS)>>>(
            bf + l * D, bb + l * D, out, l, l & 1, l != 2 ? 1 : 0);
    }
}

// round 9
// speedup vs baseline: 1.1525x; 1.1525x over previous
#include <cuda_runtime.h>
#include <cuda_bf16.h>
#include <cstdint>

#define N_USER 100000
#define N_ITEM 50000
#define N_NODES 150000
#define N_EDGES 1200000
#define D 64
#define OUTD 256
#define NEG_SLOPE 0.01f
#define EPS_NORM 1e-12f

#define SCAN_BLK 1024
#define SCAN_NBLK ((N_NODES + SCAN_BLK - 1) / SCAN_BLK)   // 147

// Scratch (device globals; no dynamic allocation)
__device__ float g_EA[N_NODES * D];       // E ping
__device__ float g_EB[N_NODES * D];       // E pong
__device__ float4 g_WdF[3 * 2048];        // dup'd Wf quads: {wf0,wf0,wf1,wf1}
__device__ float4 g_WdB[3 * 2048];        // dup'd Wb quads: {wb0,wb0,wb1,wb1}
__device__ int g_cnt[N_NODES];
__device__ int g_off[N_NODES + 1];
__device__ int g_cur[N_NODES];
__device__ float2 g_edge[N_EDGES];        // {bitcast(col), val}
__device__ int g_blksum[SCAN_NBLK];

// ---------------------------------------------------------------------------
// helpers
// ---------------------------------------------------------------------------
__device__ __forceinline__ float lrelu(float v) {
    return v >= 0.f ? v : NEG_SLOPE * v;
}
__device__ __forceinline__ unsigned long long pk2(float lo, float hi) {
    unsigned long long r;
    asm("mov.b64 %0, {%1, %2};" : "=l"(r) : "f"(lo), "f"(hi));
    return r;
}
__device__ __forceinline__ void unpk2(float& lo, float& hi, unsigned long long v) {
    asm("mov.b64 {%0, %1}, %2;" : "=f"(lo), "=f"(hi) : "l"(v));
}
__device__ __forceinline__ void fma2(unsigned long long& d, unsigned long long a,
                                     unsigned long long b) {
    asm("fma.rn.f32x2 %0, %1, %2, %0;" : "+l"(d) : "l"(a), "l"(b));
}

// ---------------------------------------------------------------------------
// CSR build: zero -> hist -> scan(3) -> scatter
// ---------------------------------------------------------------------------
__global__ void k_zero() {
    int i = blockIdx.x * blockDim.x + threadIdx.x;
    if (i < N_NODES) g_cnt[i] = 0;
}
__global__ void k_hist(const int* __restrict__ erow) {
    int e = blockIdx.x * blockDim.x + threadIdx.x;
    if (e >= N_EDGES) return;
    atomicAdd(&g_cnt[__ldg(&erow[e])], 1);
}
__global__ void k_scan1() {   // warp-scan based block scan
    __shared__ int wsum[32];
    int i = blockIdx.x * SCAN_BLK + threadIdx.x;
    int lane = threadIdx.x & 31;
    int wid = threadIdx.x >> 5;
    int v = (i < N_NODES) ? g_cnt[i] : 0;
    int s = v;
    #pragma unroll
    for (int d = 1; d < 32; d <<= 1) {
        int t = __shfl_up_sync(0xffffffffu, s, d);
        if (lane >= d) s += t;
    }
    if (lane == 31) wsum[wid] = s;
    __syncthreads();
    if (wid == 0) {
        int w = wsum[lane];
        #pragma unroll
        for (int d = 1; d < 32; d <<= 1) {
            int t = __shfl_up_sync(0xffffffffu, w, d);
            if (lane >= d) w += t;
        }
        wsum[lane] = w;
    }
    __syncthreads();
    int incl = s + (wid ? wsum[wid - 1] : 0);
    if (i < N_NODES) g_off[i] = incl - v;              // exclusive within block
    if (threadIdx.x == SCAN_BLK - 1) g_blksum[blockIdx.x] = incl;
}
__global__ void k_scan2() {   // one block of 256 >= SCAN_NBLK
    __shared__ int s[256];
    int v = (threadIdx.x < SCAN_NBLK) ? g_blksum[threadIdx.x] : 0;
    s[threadIdx.x] = v;
    __syncthreads();
    #pragma unroll
    for (int d = 1; d < 256; d <<= 1) {
        int t = (threadIdx.x >= d) ? s[threadIdx.x - d] : 0;
        __syncthreads();
        s[threadIdx.x] += t;
        __syncthreads();
    }
    if (threadIdx.x < SCAN_NBLK) g_blksum[threadIdx.x] = s[threadIdx.x] - v;
}
__global__ void k_scan3() {
    int i = blockIdx.x * SCAN_BLK + threadIdx.x;
    if (i >= N_NODES) return;
    int o = g_off[i] + g_blksum[i >> 10];
    g_off[i] = o;
    g_cur[i] = o;
    if (i == 0) g_off[N_NODES] = N_EDGES;
}
__global__ void k_scatter(const int* __restrict__ erow, const int* __restrict__ ecol,
                          const float* __restrict__ eval_) {
    int e = blockIdx.x * blockDim.x + threadIdx.x;
    if (e >= N_EDGES) return;
    int r = __ldg(&erow[e]);
    int pos = atomicAdd(&g_cur[r], 1);
    g_edge[pos] = make_float2(__int_as_float(__ldg(&ecol[e])), __ldg(&eval_[e]));
}

// ---------------------------------------------------------------------------
// kernel P: pack duplicated W quads for all 3 layers
// g_WdF[l*2048 + k*32 + j] = { Wf[j][k], Wf[j][k], Wf[j+32][k], Wf[j+32][k] }
// g_WdB likewise from Wb.
// ---------------------------------------------------------------------------
__global__ void k_prep(const float* __restrict__ Wf, const float* __restrict__ Wb) {
    int u = blockIdx.x * blockDim.x + threadIdx.x;
    if (u >= 3 * 2048) return;
    int l = u >> 11;
    int t = u & 2047;
    int k = t >> 5;
    int j = t & 31;
    const float* wf = Wf + l * D * D;
    const float* wb = Wb + l * D * D;
    float f0 = wf[j * D + k], f1 = wf[(j + 32) * D + k];
    float b0 = wb[j * D + k], b1 = wb[(j + 32) * D + k];
    g_WdF[u] = make_float4(f0, f0, f1, f1);
    g_WdB[u] = make_float4(b0, b0, b1, b1);
}

// ---------------------------------------------------------------------------
// kernel 0: build E0 = concat(user, item) into g_EA; write out[:, 0:64]
// ---------------------------------------------------------------------------
__global__ void k_init(const float* __restrict__ user, const float* __restrict__ item,
                       float* __restrict__ out) {
    int idx = blockIdx.x * blockDim.x + threadIdx.x;
    if (idx >= N_NODES * (D / 4)) return;
    int row = idx >> 4;
    int c4 = (idx & 15) << 2;
    float4 v;
    if (row < N_USER)
        v = *reinterpret_cast<const float4*>(&user[row * D + c4]);
    else
        v = *reinterpret_cast<const float4*>(&item[(row - N_USER) * D + c4]);
    *reinterpret_cast<float4*>(&g_EA[row * D + c4]) = v;
    *reinterpret_cast<float4*>(&out[row * OUTD + c4]) = v;
}

// ---------------------------------------------------------------------------
// fused layer kernel: spmm (CSR gather, registers) + dense + norm.
//   front[r] = Ein[r] + sum val*Ein[col]   (in registers)
//   o = lrelu(front @ Wf^T + bf) + lrelu((Ein*front) @ Wb^T + bb)
//   Eout <- o (if keepE) ; out[:, 64*(l+1):...] = o/||o||
// blockDim (32,8). Warp = 8 rows as 4 f32x2 row pairs.
// Dense per-k issues: 2x LDS.128 (dup'd W) + 4x LDS.128 bcast (xy) + 16 FFMA2;
// no per-k MOV duplication.
// ---------------------------------------------------------------------------
#define GROUPS (N_NODES / 8)          // 18750
#define LAYER_WARPS 8
#define LAYER_BLOCKS ((GROUPS + LAYER_WARPS - 1) / LAYER_WARPS)

__global__ __launch_bounds__(32 * LAYER_WARPS) void k_layer(
        const float* __restrict__ bf, const float* __restrict__ bb,
        float* __restrict__ out, int layer, int flip, int keepE) {
    __shared__ ulonglong2 WdF[D * 32];               // 32 KB dup'd Wf
    __shared__ ulonglong2 WdB[D * 32];               // 32 KB dup'd Wb
    __shared__ float4 xy[LAYER_WARPS][4][D];         // 32 KB

    const float* Ein = flip ? g_EB : g_EA;
    float* Eout = flip ? g_EA : g_EB;

    int tid = threadIdx.y * 32 + threadIdx.x;
    int lane = threadIdx.x;
    int ty = threadIdx.y;

    // coalesced copy of pre-dup'd W (issued first; overlaps with gather)
    {
        const ulonglong2* wf = reinterpret_cast<const ulonglong2*>(g_WdF + layer * 2048);
        const ulonglong2* wb = reinterpret_cast<const ulonglong2*>(g_WdB + layer * 2048);
        #pragma unroll
        for (int t = tid; t < 2048; t += 32 * LAYER_WARPS) {
            WdF[t] = wf[t];
            WdB[t] = wb[t];
        }
    }

    int group = blockIdx.x * LAYER_WARPS + ty;
    const float2* E2 = reinterpret_cast<const float2*>(Ein);

    if (group < GROUPS) {
        int rb = group * 8;
        // phase 1: gather front for 4 row pairs, stage xy
        #pragma unroll
        for (int p = 0; p < 4; p++) {
            int r0 = rb + 2 * p;
            int r1 = r0 + 1;
            int i0 = __ldg(&g_off[r0]);
            int n0 = __ldg(&g_off[r0 + 1]);
            int i1 = __ldg(&g_off[r1]);
            int n1 = __ldg(&g_off[r1 + 1]);
            float2 e0v = E2[r0 * 32 + lane];
            float2 e1v = E2[r1 * 32 + lane];
            float2 acc0 = e0v;                        // +I term
            float2 acc1 = e1v;
            int m = min(n0 - i0, n1 - i1);
            for (int t = 0; t < m; t++) {
                float2 p0 = g_edge[i0 + t];
                float2 p1 = g_edge[i1 + t];
                int c0 = __float_as_int(p0.x);
                int c1 = __float_as_int(p1.x);
                float2 x0 = E2[c0 * 32 + lane];
                float2 x1 = E2[c1 * 32 + lane];
                acc0.x = fmaf(p0.y, x0.x, acc0.x);
                acc0.y = fmaf(p0.y, x0.y, acc0.y);
                acc1.x = fmaf(p1.y, x1.x, acc1.x);
                acc1.y = fmaf(p1.y, x1.y, acc1.y);
            }
            for (i0 += m; i0 < n0; i0++) {
                float2 p0 = g_edge[i0];
                int c0 = __float_as_int(p0.x);
                float2 x0 = E2[c0 * 32 + lane];
                acc0.x = fmaf(p0.y, x0.x, acc0.x);
                acc0.y = fmaf(p0.y, x0.y, acc0.y);
            }
            for (i1 += m; i1 < n1; i1++) {
                float2 p1 = g_edge[i1];
                int c1 = __float_as_int(p1.x);
                float2 x1 = E2[c1 * 32 + lane];
                acc1.x = fmaf(p1.y, x1.x, acc1.x);
                acc1.y = fmaf(p1.y, x1.y, acc1.y);
            }
            xy[ty][p][2 * lane] =
                make_float4(acc0.x, acc1.x, acc0.x * e0v.x, acc1.x * e1v.x);
            xy[ty][p][2 * lane + 1] =
                make_float4(acc0.y, acc1.y, acc0.y * e0v.y, acc1.y * e1v.y);
        }
    }
    __syncthreads();
    if (group >= GROUPS) return;
    int rb = group * 8;

    float bfv0 = bf[lane], bfv1 = bf[lane + 32];
    float bbv0 = bb[lane], bbv1 = bb[lane + 32];

    unsigned long long sf0[4], sf1[4], sb0[4], sb1[4];
    #pragma unroll
    for (int p = 0; p < 4; p++) {
        sf0[p] = pk2(bfv0, bfv0);
        sf1[p] = pk2(bfv1, bfv1);
        sb0[p] = pk2(bbv0, bbv0);
        sb1[p] = pk2(bbv1, bbv1);
    }

    #pragma unroll 4
    for (int k = 0; k < D; k++) {
        ulonglong2 wf = WdF[k * 32 + lane];   // {wf0p, wf1p}
        ulonglong2 wb = WdB[k * 32 + lane];   // {wb0p, wb1p}
        #pragma unroll
        for (int p = 0; p < 4; p++) {
            ulonglong2 v = *reinterpret_cast<const ulonglong2*>(&xy[ty][p][k]);
            fma2(sf0[p], v.x, wf.x);
            fma2(sf1[p], v.x, wf.y);
            fma2(sb0[p], v.y, wb.x);
            fma2(sb1[p], v.y, wb.y);
        }
    }

    int ocol = (layer + 1) * D;
    #pragma unroll
    for (int p = 0; p < 4; p++) {
        float f0lo, f0hi, f1lo, f1hi, b0lo, b0hi, b1lo, b1hi;
        unpk2(f0lo, f0hi, sf0[p]);
        unpk2(f1lo, f1hi, sf1[p]);
        unpk2(b0lo, b0hi, sb0[p]);
        unpk2(b1lo, b1hi, sb1[p]);

        int row0 = rb + 2 * p;
        int row1 = row0 + 1;

        float o00 = lrelu(f0lo) + lrelu(b0lo);
        float o01 = lrelu(f1lo) + lrelu(b1lo);
        float o10 = lrelu(f0hi) + lrelu(b0hi);
        float o11 = lrelu(f1hi) + lrelu(b1hi);

        float ss0 = o00 * o00 + o01 * o01;
        float ss1 = o10 * o10 + o11 * o11;
        #pragma unroll
        for (int d = 16; d > 0; d >>= 1) {
            ss0 += __shfl_xor_sync(0xffffffffu, ss0, d);
            ss1 += __shfl_xor_sync(0xffffffffu, ss1, d);
        }
        float inv0 = 1.f / fmaxf(sqrtf(ss0), EPS_NORM);
        float inv1 = 1.f / fmaxf(sqrtf(ss1), EPS_NORM);

        if (keepE) {
            Eout[row0 * D + lane] = o00;
            Eout[row0 * D + 32 + lane] = o01;
            Eout[row1 * D + lane] = o10;
            Eout[row1 * D + 32 + lane] = o11;
        }

        out[row0 * OUTD + ocol + lane] = o00 * inv0;
        out[row0 * OUTD + ocol + 32 + lane] = o01 * inv0;
        out[row1 * OUTD + ocol + lane] = o10 * inv1;
        out[row1 * OUTD + ocol + 32 + lane] = o11 * inv1;
    }
}

// ---------------------------------------------------------------------------
extern "C" void kernel_launch(void* const* d_in, const int* in_sizes, int n_in,
                              void* d_out, int out_size) {
    const float* user = (const float*)d_in[0];
    const float* item = (const float*)d_in[1];
    const int* erow = (const int*)d_in[2];
    const int* ecol = (const int*)d_in[3];
    const float* eval_ = (const float*)d_in[4];
    const float* Wf = (const float*)d_in[5];
    const float* bf = (const float*)d_in[6];
    const float* Wb = (const float*)d_in[7];
    const float* bb = (const float*)d_in[8];
    float* out = (float*)d_out;

    const int vec_elems = N_NODES * (D / 4);
    const int vec_blocks = (vec_elems + 255) / 256;
    const int edge_blocks = (N_EDGES + 255) / 256;
    const int node_blocks = (N_NODES + 255) / 256;

    // CSR build (per replay; deterministic)
    k_zero<<<node_blocks, 256>>>();
    k_hist<<<edge_blocks, 256>>>(erow);
    k_scan1<<<SCAN_NBLK, SCAN_BLK>>>();
    k_scan2<<<1, 256>>>();
    k_scan3<<<SCAN_NBLK, SCAN_BLK>>>();
    k_scatter<<<edge_blocks, 256>>>(erow, ecol, eval_);

    k_prep<<<24, 256>>>(Wf, Wb);
    k_init<<<vec_blocks, 256>>>(user, item, out);
    for (int l = 0; l < 3; l++) {
        k_layer<<<LAYER_BLOCKS, dim3(32, LAYER_WARPS)>>>(
            bf + l * D, bb + l * D, out, l, l & 1, l != 2 ? 1 : 0);
    }
}

// round 11
// speedup vs baseline: 1.5291x; 1.3268x over previous
#include <cuda_runtime.h>
#include <cuda_bf16.h>
#include <cstdint>

#define N_USER 100000
#define N_ITEM 50000
#define N_NODES 150000
#define N_EDGES 1200000
#define D 64
#define OUTD 256
#define NEG_SLOPE 0.01f
#define EPS_NORM 1e-12f

#define SCAN_BLK 1024
#define SCAN_NBLK ((N_NODES + SCAN_BLK - 1) / SCAN_BLK)   // 147

// Scratch (device globals; no dynamic allocation)
__device__ float g_EA[N_NODES * D];       // E ping
__device__ float g_EB[N_NODES * D];       // E pong
__device__ float4 g_Wpack[3 * 2048];      // packed W quads per layer
__device__ int g_cnt[N_NODES];
__device__ int g_off[N_NODES + 1];
__device__ int g_cur[N_NODES];
__device__ float2 g_edge[N_EDGES];        // {bitcast(col), val}
__device__ int g_blksum[SCAN_NBLK];

// ---------------------------------------------------------------------------
// helpers
// ---------------------------------------------------------------------------
__device__ __forceinline__ float lrelu(float v) {
    return v >= 0.f ? v : NEG_SLOPE * v;
}
__device__ __forceinline__ unsigned long long pk2(float lo, float hi) {
    unsigned long long r;
    asm("mov.b64 %0, {%1, %2};" : "=l"(r) : "f"(lo), "f"(hi));
    return r;
}
__device__ __forceinline__ void unpk2(float& lo, float& hi, unsigned long long v) {
    asm("mov.b64 {%0, %1}, %2;" : "=f"(lo), "=f"(hi) : "l"(v));
}
__device__ __forceinline__ void fma2(unsigned long long& d, unsigned long long a,
                                     unsigned long long b) {
    asm("fma.rn.f32x2 %0, %1, %2, %0;" : "+l"(d) : "l"(a), "l"(b));
}

// ---------------------------------------------------------------------------
// CSR build: zero -> hist -> scan(3) -> scatter
// ---------------------------------------------------------------------------
__global__ void k_zero() {
    int i = blockIdx.x * blockDim.x + threadIdx.x;
    if (i < N_NODES) g_cnt[i] = 0;
}
__global__ void k_hist(const int* __restrict__ erow) {
    int e = blockIdx.x * blockDim.x + threadIdx.x;
    if (e >= N_EDGES) return;
    atomicAdd(&g_cnt[__ldg(&erow[e])], 1);
}
__global__ void k_scan1() {   // warp-scan based block scan
    __shared__ int wsum[32];
    int i = blockIdx.x * SCAN_BLK + threadIdx.x;
    int lane = threadIdx.x & 31;
    int wid = threadIdx.x >> 5;
    int v = (i < N_NODES) ? g_cnt[i] : 0;
    int s = v;
    #pragma unroll
    for (int d = 1; d < 32; d <<= 1) {
        int t = __shfl_up_sync(0xffffffffu, s, d);
        if (lane >= d) s += t;
    }
    if (lane == 31) wsum[wid] = s;
    __syncthreads();
    if (wid == 0) {
        int w = wsum[lane];
        #pragma unroll
        for (int d = 1; d < 32; d <<= 1) {
            int t = __shfl_up_sync(0xffffffffu, w, d);
            if (lane >= d) w += t;
        }
        wsum[lane] = w;
    }
    __syncthreads();
    int incl = s + (wid ? wsum[wid - 1] : 0);
    if (i < N_NODES) g_off[i] = incl - v;              // exclusive within block
    if (threadIdx.x == SCAN_BLK - 1) g_blksum[blockIdx.x] = incl;
}
__global__ void k_scan2() {   // one block of 256 >= SCAN_NBLK
    __shared__ int s[256];
    int v = (threadIdx.x < SCAN_NBLK) ? g_blksum[threadIdx.x] : 0;
    s[threadIdx.x] = v;
    __syncthreads();
    #pragma unroll
    for (int d = 1; d < 256; d <<= 1) {
        int t = (threadIdx.x >= d) ? s[threadIdx.x - d] : 0;
        __syncthreads();
        s[threadIdx.x] += t;
        __syncthreads();
    }
    if (threadIdx.x < SCAN_NBLK) g_blksum[threadIdx.x] = s[threadIdx.x] - v;
}
__global__ void k_scan3() {
    int i = blockIdx.x * SCAN_BLK + threadIdx.x;
    if (i >= N_NODES) return;
    int o = g_off[i] + g_blksum[i >> 10];
    g_off[i] = o;
    g_cur[i] = o;
    if (i == 0) g_off[N_NODES] = N_EDGES;
}
__global__ void k_scatter(const int* __restrict__ erow, const int* __restrict__ ecol,
                          const float* __restrict__ eval_) {
    int e = blockIdx.x * blockDim.x + threadIdx.x;
    if (e >= N_EDGES) return;
    int r = __ldg(&erow[e]);
    int pos = atomicAdd(&g_cur[r], 1);
    g_edge[pos] = make_float2(__int_as_float(__ldg(&ecol[e])), __ldg(&eval_[e]));
}

// ---------------------------------------------------------------------------
// kernel P: pack W for all 3 layers
// g_Wpack[l*2048 + k*32 + j] = { Wf[j][k], Wf[j+32][k], Wb[j][k], Wb[j+32][k] }
// ---------------------------------------------------------------------------
__global__ void k_prep(const float* __restrict__ Wf, const float* __restrict__ Wb) {
    int u = blockIdx.x * blockDim.x + threadIdx.x;
    if (u >= 3 * 2048) return;
    int l = u >> 11;
    int t = u & 2047;
    int k = t >> 5;
    int j = t & 31;
    const float* wf = Wf + l * D * D;
    const float* wb = Wb + l * D * D;
    g_Wpack[u] = make_float4(wf[j * D + k], wf[(j + 32) * D + k],
                             wb[j * D + k], wb[(j + 32) * D + k]);
}

// ---------------------------------------------------------------------------
// kernel 0: build E0 = concat(user, item) into g_EA; write out[:, 0:64]
// ---------------------------------------------------------------------------
__global__ void k_init(const float* __restrict__ user, const float* __restrict__ item,
                       float* __restrict__ out) {
    int idx = blockIdx.x * blockDim.x + threadIdx.x;
    if (idx >= N_NODES * (D / 4)) return;
    int row = idx >> 4;
    int c4 = (idx & 15) << 2;
    float4 v;
    if (row < N_USER)
        v = *reinterpret_cast<const float4*>(&user[row * D + c4]);
    else
        v = *reinterpret_cast<const float4*>(&item[(row - N_USER) * D + c4]);
    *reinterpret_cast<float4*>(&g_EA[row * D + c4]) = v;
    *reinterpret_cast<float4*>(&out[row * OUTD + c4]) = v;
}

// ---------------------------------------------------------------------------
// fused layer kernel: spmm (CSR gather, registers) + dense + norm.
//   front[r] = Ein[r] + sum val*Ein[col]   (in registers)
//   o = lrelu(front @ Wf^T + bf) + lrelu((Ein*front) @ Wb^T + bb)
//   Eout <- o (if keepE) ; out[:, 64*(l+1):...] = o/||o||
// blockDim (32,8). Warp = 8 rows as 4 f32x2 row pairs.
// W copy + __syncthreads happen BEFORE gather: after that point warps flow
// gather -> dense -> epilogue independently (cross-warp phase mixing).
// ---------------------------------------------------------------------------
#define GROUPS (N_NODES / 8)          // 18750
#define LAYER_WARPS 8
#define LAYER_BLOCKS ((GROUPS + LAYER_WARPS - 1) / LAYER_WARPS)

__global__ __launch_bounds__(32 * LAYER_WARPS) void k_layer(
        const float* __restrict__ bf, const float* __restrict__ bb,
        float* __restrict__ out, int layer, int flip, int keepE) {
    __shared__ float4 Wc[D * 32];                    // 32 KB, packed quads
    __shared__ float4 xy[LAYER_WARPS][4][D];         // 32 KB

    const float* Ein = flip ? g_EB : g_EA;
    float* Eout = flip ? g_EA : g_EB;

    int tid = threadIdx.y * 32 + threadIdx.x;
    int lane = threadIdx.x;
    int ty = threadIdx.y;

    // coalesced copy of pre-packed W; sync BEFORE gather so warps are
    // independent afterwards
    const float4* wsrc = g_Wpack + layer * 2048;
    #pragma unroll
    for (int t = tid; t < 2048; t += 32 * LAYER_WARPS) Wc[t] = wsrc[t];
    __syncthreads();

    int group = blockIdx.x * LAYER_WARPS + ty;
    const float2* E2 = reinterpret_cast<const float2*>(Ein);
    if (group >= GROUPS) return;
    int rb = group * 8;

    // phase 1: gather front for 4 row pairs, stage xy (per-warp smem)
    #pragma unroll
    for (int p = 0; p < 4; p++) {
        int r0 = rb + 2 * p;
        int r1 = r0 + 1;
        int i0 = __ldg(&g_off[r0]);
        int n0 = __ldg(&g_off[r0 + 1]);
        int i1 = __ldg(&g_off[r1]);
        int n1 = __ldg(&g_off[r1 + 1]);
        float2 e0v = E2[r0 * 32 + lane];
        float2 e1v = E2[r1 * 32 + lane];
        float2 acc0 = e0v;                        // +I term
        float2 acc1 = e1v;
        int m = min(n0 - i0, n1 - i1);
        for (int t = 0; t < m; t++) {
            float2 p0 = g_edge[i0 + t];
            float2 p1 = g_edge[i1 + t];
            int c0 = __float_as_int(p0.x);
            int c1 = __float_as_int(p1.x);
            float2 x0 = E2[c0 * 32 + lane];
            float2 x1 = E2[c1 * 32 + lane];
            acc0.x = fmaf(p0.y, x0.x, acc0.x);
            acc0.y = fmaf(p0.y, x0.y, acc0.y);
            acc1.x = fmaf(p1.y, x1.x, acc1.x);
            acc1.y = fmaf(p1.y, x1.y, acc1.y);
        }
        for (i0 += m; i0 < n0; i0++) {
            float2 p0 = g_edge[i0];
            int c0 = __float_as_int(p0.x);
            float2 x0 = E2[c0 * 32 + lane];
            acc0.x = fmaf(p0.y, x0.x, acc0.x);
            acc0.y = fmaf(p0.y, x0.y, acc0.y);
        }
        for (i1 += m; i1 < n1; i1++) {
            float2 p1 = g_edge[i1];
            int c1 = __float_as_int(p1.x);
            float2 x1 = E2[c1 * 32 + lane];
            acc1.x = fmaf(p1.y, x1.x, acc1.x);
            acc1.y = fmaf(p1.y, x1.y, acc1.y);
        }
        xy[ty][p][2 * lane] =
            make_float4(acc0.x, acc1.x, acc0.x * e0v.x, acc1.x * e1v.x);
        xy[ty][p][2 * lane + 1] =
            make_float4(acc0.y, acc1.y, acc0.y * e0v.y, acc1.y * e1v.y);
    }
    __syncwarp();

    // phase 2: dense
    float bfv0 = bf[lane], bfv1 = bf[lane + 32];
    float bbv0 = bb[lane], bbv1 = bb[lane + 32];

    unsigned long long sf0[4], sf1[4], sb0[4], sb1[4];
    #pragma unroll
    for (int p = 0; p < 4; p++) {
        sf0[p] = pk2(bfv0, bfv0);
        sf1[p] = pk2(bfv1, bfv1);
        sb0[p] = pk2(bbv0, bbv0);
        sb1[p] = pk2(bbv1, bbv1);
    }

    #pragma unroll 4
    for (int k = 0; k < D; k++) {
        float4 w = Wc[k * 32 + lane];
        unsigned long long wf0p = pk2(w.x, w.x);
        unsigned long long wf1p = pk2(w.y, w.y);
        unsigned long long wb0p = pk2(w.z, w.z);
        unsigned long long wb1p = pk2(w.w, w.w);
        #pragma unroll
        for (int p = 0; p < 4; p++) {
            ulonglong2 v = *reinterpret_cast<const ulonglong2*>(&xy[ty][p][k]);
            fma2(sf0[p], v.x, wf0p);
            fma2(sf1[p], v.x, wf1p);
            fma2(sb0[p], v.y, wb0p);
            fma2(sb1[p], v.y, wb1p);
        }
    }

    // phase 3: epilogue
    int ocol = (layer + 1) * D;
    #pragma unroll
    for (int p = 0; p < 4; p++) {
        float f0lo, f0hi, f1lo, f1hi, b0lo, b0hi, b1lo, b1hi;
        unpk2(f0lo, f0hi, sf0[p]);
        unpk2(f1lo, f1hi, sf1[p]);
        unpk2(b0lo, b0hi, sb0[p]);
        unpk2(b1lo, b1hi, sb1[p]);

        int row0 = rb + 2 * p;
        int row1 = row0 + 1;

        float o00 = lrelu(f0lo) + lrelu(b0lo);
        float o01 = lrelu(f1lo) + lrelu(b1lo);
        float o10 = lrelu(f0hi) + lrelu(b0hi);
        float o11 = lrelu(f1hi) + lrelu(b1hi);

        float ss0 = o00 * o00 + o01 * o01;
        float ss1 = o10 * o10 + o11 * o11;
        #pragma unroll
        for (int d = 16; d > 0; d >>= 1) {
            ss0 += __shfl_xor_sync(0xffffffffu, ss0, d);
            ss1 += __shfl_xor_sync(0xffffffffu, ss1, d);
        }
        float inv0 = 1.f / fmaxf(sqrtf(ss0), EPS_NORM);
        float inv1 = 1.f / fmaxf(sqrtf(ss1), EPS_NORM);

        if (keepE) {
            Eout[row0 * D + lane] = o00;
            Eout[row0 * D + 32 + lane] = o01;
            Eout[row1 * D + lane] = o10;
            Eout[row1 * D + 32 + lane] = o11;
        }

        out[row0 * OUTD + ocol + lane] = o00 * inv0;
        out[row0 * OUTD + ocol + 32 + lane] = o01 * inv0;
        out[row1 * OUTD + ocol + lane] = o10 * inv1;
        out[row1 * OUTD + ocol + 32 + lane] = o11 * inv1;
    }
}

// ---------------------------------------------------------------------------
extern "C" void kernel_launch(void* const* d_in, const int* in_sizes, int n_in,
                              void* d_out, int out_size) {
    const float* user = (const float*)d_in[0];
    const float* item = (const float*)d_in[1];
    const int* erow = (const int*)d_in[2];
    const int* ecol = (const int*)d_in[3];
    const float* eval_ = (const float*)d_in[4];
    const float* Wf = (const float*)d_in[5];
    const float* bf = (const float*)d_in[6];
    const float* Wb = (const float*)d_in[7];
    const float* bb = (const float*)d_in[8];
    float* out = (float*)d_out;

    const int vec_elems = N_NODES * (D / 4);
    const int vec_blocks = (vec_elems + 255) / 256;
    const int edge_blocks = (N_EDGES + 255) / 256;
    const int node_blocks = (N_NODES + 255) / 256;

    // CSR build (per replay; deterministic)
    k_zero<<<node_blocks, 256>>>();
    k_hist<<<edge_blocks, 256>>>(erow);
    k_scan1<<<SCAN_NBLK, SCAN_BLK>>>();
    k_scan2<<<1, 256>>>();
    k_scan3<<<SCAN_NBLK, SCAN_BLK>>>();
    k_scatter<<<edge_blocks, 256>>>(erow, ecol, eval_);

    k_prep<<<24, 256>>>(Wf, Wb);
    k_init<<<vec_blocks, 256>>>(user, item, out);
    for (int l = 0; l < 3; l++) {
        k_layer<<<LAYER_BLOCKS, dim3(32, LAYER_WARPS)>>>(
            bf + l * D, bb + l * D, out, l, l & 1, l != 2 ? 1 : 0);
    }
}